// round 3
// baseline (speedup 1.0000x reference)
#include <cuda_runtime.h>

// Problem constants
#define B_ROWS   65536
#define C_COLS   300
#define A_DIM    32
#define XSTRIDE  600

#define NWARPS   12
#define THREADS  (NWARPS * 32)
#define RPG      8                          // rows per warp per group
#define NGROUPS  (B_ROWS / RPG)             // 8192
#define GRID     296                        // 2 CTAs per SM, uniform
#define TOTWARPS (GRID * NWARPS)            // 3552

#define IDXCAP   64                         // nonzero-option cap (mean ~16, P(exceed)~1e-55)

// SMEM: P[75][32] float4 (quad-packed W, conflict-free) + per-warp {ap[8][32], idx[8][64], sc[64]}
#define P_FLOATS    (75 * 32 * 4)                       // 9600
#define WARP_FLOATS (RPG * 32 + RPG * IDXCAP + IDXCAP)  // 256 + 512 + 64 = 832
#define SMEM_FLOATS (P_FLOATS + NWARPS * WARP_FLOATS)   // 19584
#define SMEM_BYTES  (SMEM_FLOATS * 4)                   // 78336 B -> 2 CTAs/SM

__device__ __forceinline__ void fma2(unsigned long long& d,
                                     unsigned long long a,
                                     unsigned long long b) {
    asm("fma.rn.f32x2 %0, %1, %2, %0;" : "+l"(d) : "l"(a), "l"(b));
}
__device__ __forceinline__ float2 unpack2(unsigned long long v) {
    float2 r;
    asm("mov.b64 {%0, %1}, %2;" : "=f"(r.x), "=f"(r.y) : "l"(v));
    return r;
}

__global__ __launch_bounds__(THREADS, 2)
void draftbot_kernel(const float* __restrict__ X,
                     const float* __restrict__ W,
                     float* __restrict__ Out)
{
    extern __shared__ float smem[];
    const int tid  = threadIdx.x;
    const int lane = tid & 31;
    const int warp = tid >> 5;

    // P[t][a] = {W[4t][a], W[4t+1][a], W[4t+2][a], W[4t+3][a]}
    for (int e = tid; e < C_COLS * A_DIM; e += THREADS) {
        int c = e >> 5, a = e & 31;
        smem[((c >> 2) * 32 + a) * 4 + (c & 3)] = W[e];
    }
    __syncthreads();

    const ulonglong2* Pq = (const ulonglong2*)smem;            // [75][32]
    float* wbase  = smem + P_FLOATS + warp * WARP_FLOATS;
    float* apbuf  = wbase;                                     // [8][32]
    int*   idxbuf = (int*)(wbase + RPG * 32);                  // [8][64]
    float* scbuf  = wbase + RPG * 32 + RPG * IDXCAP;           // [64]

    const unsigned FULL   = 0xffffffffu;
    const unsigned ltmask = (1u << lane) - 1u;
    const int qid = lane >> 3;          // phase-2: column slot 0..3
    const int sub = lane & 7;           // phase-2: 8 lanes per column

    // Static interleaved schedule: ~4% per-SM imbalance, no atomics.
    const int gwid = warp * GRID + blockIdx.x;

    for (int g = gwid; g < NGROUPS; g += TOTWARPS) {
        const int row0 = g * RPG;
        int cnt[RPG];

        // ---------- compaction: indices of nonzero options ----------
        #pragma unroll 1
        for (int r = 0; r < RPG; r++) {
            const float4* osrc = (const float4*)(X + (size_t)(row0 + r) * XSTRIDE);
            int cn = 0;
            #pragma unroll
            for (int t = 0; t < 3; t++) {
                int  gi = lane + 32 * t;
                bool v  = gi < 75;
                float4 ov = v ? osrc[gi] : make_float4(0.f, 0.f, 0.f, 0.f);
                float ovals[4] = {ov.x, ov.y, ov.z, ov.w};
                #pragma unroll
                for (int i = 0; i < 4; i++) {
                    bool f = (ovals[i] != 0.0f);
                    unsigned mm = __ballot_sync(FULL, f);
                    if (f) {
                        int pos = cn + __popc(mm & ltmask);
                        if (pos < IDXCAP) idxbuf[r * IDXCAP + pos] = 4 * gi + i;
                    }
                    cn += __popc(mm);
                }
            }
            cnt[r] = (cn < IDXCAP) ? cn : IDXCAP;
        }
        __syncwarp();

        // ---------- phase 1: ap = cards @ W + 1   (lane = a) ----------
        unsigned long long acc[RPG];
        #pragma unroll
        for (int r = 0; r < RPG; r++) acc[r] = 0ull;

        const float* cbase = X + (size_t)row0 * XSTRIDE + C_COLS;
        #pragma unroll 3
        for (int t = 0; t < 75; t++) {
            ulonglong2 wv = Pq[t * 32 + lane];          // LDS.128, conflict-free
            #pragma unroll
            for (int r = 0; r < RPG; r++) {
                // uniform-address broadcast LDG.128
                ulonglong2 cv = *(const ulonglong2*)(cbase + r * XSTRIDE + 4 * t);
                fma2(acc[r], cv.x, wv.x);
                fma2(acc[r], cv.y, wv.y);
            }
        }
        #pragma unroll
        for (int r = 0; r < RPG; r++) {
            float2 a2 = unpack2(acc[r]);
            apbuf[r * 32 + lane] = a2.x + a2.y + 1.0f;
        }
        __syncwarp();

        // ---------- phase 2: sparse scores (8 lanes/col, 4 cols in flight) ----------
        #pragma unroll 1
        for (int r = 0; r < RPG; r++) {
            const int cn = cnt[r];

            // scores -> scbuf
            float4 av = ((const float4*)(apbuf + r * 32))[sub];   // broadcast LDS.128
            const int nch = (cn + 3) >> 2;
            #pragma unroll 2
            for (int ch = 0; ch < nch; ch++) {
                int  j   = ch * 4 + qid;
                bool val = j < cn;
                int  c   = val ? idxbuf[r * IDXCAP + j] : 0;
                float4 wv = *(const float4*)(W + c * A_DIM + sub * 4);  // 1 line per octet
                float p = av.x * wv.x + av.y * wv.y + av.z * wv.z + av.w * wv.w;
                p += __shfl_xor_sync(FULL, p, 1);
                p += __shfl_xor_sync(FULL, p, 2);
                p += __shfl_xor_sync(FULL, p, 4);
                if (val && sub == 0) scbuf[j] = p;
            }
            __syncwarp();

            // masked log-softmax over the row (zeros always present -> m >= 0)
            int  j0 = lane, j1 = lane + 32;
            bool v0 = j0 < cn, v1 = j1 < cn;
            float s0 = v0 ? scbuf[j0] : 0.0f;
            float s1 = v1 ? scbuf[j1] : 0.0f;
            int   c0 = v0 ? idxbuf[r * IDXCAP + j0] : -1;
            int   c1 = v1 ? idxbuf[r * IDXCAP + j1] : -1;

            float m = fmaxf(fmaxf(s0, s1), 0.0f);
            #pragma unroll
            for (int o = 16; o > 0; o >>= 1) m = fmaxf(m, __shfl_xor_sync(FULL, m, o));

            float g0 = (s0 > 0.f) ? 1.f : ((s0 < 0.f) ? -1.f : 0.f);
            float g1 = (s1 > 0.f) ? 1.f : ((s1 < 0.f) ? -1.f : 0.f);
            float sum = g0 * __expf(s0 - m * g0) + g1 * __expf(s1 - m * g1);
            #pragma unroll
            for (int o = 16; o > 0; o >>= 1) sum += __shfl_xor_sync(FULL, sum, o);
            float lse = __logf(sum);

            // zero-fill row, warp fence, scatter log-probs
            float* orow = Out + (size_t)(row0 + r) * C_COLS;
            #pragma unroll
            for (int t = 0; t < 3; t++) {
                int gi = lane + 32 * t;
                if (gi < 75) *(float4*)(orow + 4 * gi) = make_float4(0.f, 0.f, 0.f, 0.f);
            }
            __syncwarp();
            if (c0 >= 0) orow[c0] = g0 * ((s0 - m * g0) - lse);
            if (c1 >= 0) orow[c1] = g1 * ((s1 - m * g1) - lse);
        }
    }
}

extern "C" void kernel_launch(void* const* d_in, const int* in_sizes, int n_in,
                              void* d_out, int out_size)
{
    const float* X = (const float*)d_in[0];
    const float* W = (const float*)d_in[1];
    if (n_in >= 2 && in_sizes[0] < in_sizes[1]) {   // defensively order by size
        const float* t = X; X = W; W = t;
    }
    float* Out = (float*)d_out;

    cudaFuncSetAttribute(draftbot_kernel,
                         cudaFuncAttributeMaxDynamicSharedMemorySize, SMEM_BYTES);
    draftbot_kernel<<<GRID, THREADS, SMEM_BYTES>>>(X, W, Out);
}

// round 4
// speedup vs baseline: 1.2549x; 1.2549x over previous
#include <cuda_runtime.h>
#include <cstdint>

// Problem constants
#define B_ROWS   65536
#define C_COLS   300
#define A_DIM    32
#define XSTRIDE  600

#define NWARPS   16
#define THREADS  512
#define RPG      4                           // rows per warp
#define GROUP_ROWS 64                        // NWARPS * RPG
#define NGROUPS  (B_ROWS / GROUP_ROWS)       // 1024
#define GRID     148

#define IDXCAP   64                          // nonzero-option cap (mean ~16)
#define CSTR     304                         // cards row stride in floats (16B aligned)

// SMEM: P[75][32]float4 | cards[2][64][304] | per-warp {ap[4][32], idx[4][64], sc[64]}
#define P_FLOATS     9600
#define CARDS_FLOATS (GROUP_ROWS * CSTR)                  // 19456
#define PW_FLOATS    (RPG*32 + RPG*IDXCAP + IDXCAP)       // 448
#define SMEM_FLOATS  (P_FLOATS + 2*CARDS_FLOATS + NWARPS*PW_FLOATS)  // 55680
#define SMEM_BYTES   (SMEM_FLOATS * 4)                    // 222720 B (1 CTA/SM)

__device__ __forceinline__ void fma2(unsigned long long& d,
                                     unsigned long long a,
                                     unsigned long long b) {
    asm("fma.rn.f32x2 %0, %1, %2, %0;" : "+l"(d) : "l"(a), "l"(b));
}
__device__ __forceinline__ float2 unpack2(unsigned long long v) {
    float2 r;
    asm("mov.b64 {%0, %1}, %2;" : "=f"(r.x), "=f"(r.y) : "l"(v));
    return r;
}
__device__ __forceinline__ void cp16(uint32_t saddr, const float* gaddr) {
    asm volatile("cp.async.cg.shared.global [%0], [%1], 16;" :: "r"(saddr), "l"(gaddr));
}
__device__ __forceinline__ void cp_commit() {
    asm volatile("cp.async.commit_group;");
}
template<int N> __device__ __forceinline__ void cp_wait() {
    asm volatile("cp.async.wait_group %0;" :: "n"(N));
}

__global__ __launch_bounds__(THREADS, 1)
void draftbot_kernel(const float* __restrict__ X,
                     const float* __restrict__ W,
                     float* __restrict__ Out)
{
    extern __shared__ float smem[];
    const int tid  = threadIdx.x;
    const int lane = tid & 31;
    const int warp = tid >> 5;

    const uint32_t smem_u32 = (uint32_t)__cvta_generic_to_shared(smem);
    float* cardsA = smem + P_FLOATS;                 // [64][304] x2
    float* pwbase = smem + P_FLOATS + 2 * CARDS_FLOATS + warp * PW_FLOATS;
    float* apbuf  = pwbase;                          // [4][32]
    int*   idxbuf = (int*)(pwbase + RPG * 32);       // [4][64]
    float* scbuf  = pwbase + RPG * 32 + RPG * IDXCAP;// [64]

    // ---- stage cards of group g into buffer b via cp.async (CTA-cooperative) ----
    auto stage = [&](int g, int b) {
        uint32_t sb = smem_u32 + (P_FLOATS + b * CARDS_FLOATS) * 4;
        const float* gb = X + (size_t)g * GROUP_ROWS * XSTRIDE + C_COLS;
        #pragma unroll
        for (int t = 0; t < 10; t++) {
            int idx = tid + THREADS * t;             // 0..4799 = 64 rows x 75 chunks
            if (idx < GROUP_ROWS * 75) {
                int row = idx / 75, ch = idx - row * 75;
                cp16(sb + (uint32_t)(row * CSTR + ch * 4) * 4,
                     gb + (size_t)row * XSTRIDE + ch * 4);
            }
        }
        cp_commit();
    };

    int g = blockIdx.x;
    if (g < NGROUPS) stage(g, 0);

    // Build P[t][a] = {W[4t][a],W[4t+1][a],W[4t+2][a],W[4t+3][a]} (conflict-free phase-1 W)
    for (int e = tid; e < C_COLS * A_DIM; e += THREADS) {
        int c = e >> 5, a = e & 31;
        smem[((c >> 2) * 32 + a) * 4 + (c & 3)] = W[e];
    }
    __syncthreads();

    const ulonglong2* Pq = (const ulonglong2*)smem;  // [75][32]
    const unsigned FULL   = 0xffffffffu;
    const unsigned ltmask = (1u << lane) - 1u;
    const int qid = lane >> 3;                       // phase-2 column slot
    const int sub = lane & 7;                        // 8 lanes per column

    int it = 0;
    for (; g < NGROUPS; g += GRID, it++) {
        const int  b        = it & 1;
        const bool havenext = (g + GRID < NGROUPS);
        if (havenext) stage(g + GRID, b ^ 1);

        const int row0 = g * GROUP_ROWS + warp * RPG;   // this warp's 4 rows

        // ---------- compaction (batched loads for MLP, overlaps cp.async) ----------
        float4 ov[RPG][3];
        #pragma unroll
        for (int r = 0; r < RPG; r++) {
            const float4* osrc = (const float4*)(X + (size_t)(row0 + r) * XSTRIDE);
            #pragma unroll
            for (int t = 0; t < 3; t++) {
                int gi = lane + 32 * t;
                ov[r][t] = (gi < 75) ? osrc[gi] : make_float4(0.f, 0.f, 0.f, 0.f);
            }
        }
        int cnt[RPG];
        #pragma unroll
        for (int r = 0; r < RPG; r++) {
            int cn = 0;
            #pragma unroll
            for (int t = 0; t < 3; t++) {
                float vals[4] = {ov[r][t].x, ov[r][t].y, ov[r][t].z, ov[r][t].w};
                #pragma unroll
                for (int i = 0; i < 4; i++) {
                    bool f = (vals[i] != 0.0f);
                    unsigned mm = __ballot_sync(FULL, f);
                    if (f) {
                        int pos = cn + __popc(mm & ltmask);
                        if (pos < IDXCAP) idxbuf[r * IDXCAP + pos] = 4 * (lane + 32 * t) + i;
                    }
                    cn += __popc(mm);
                }
            }
            cnt[r] = (cn < IDXCAP) ? cn : IDXCAP;
        }

        if (havenext) cp_wait<1>(); else cp_wait<0>();
        __syncthreads();                              // cards[b] ready for all warps

        // ---------- phase 1: ap = cards @ W + 1  (lane = a) ----------
        unsigned long long acc[RPG];
        #pragma unroll
        for (int r = 0; r < RPG; r++) acc[r] = 0ull;

        const float* cb = smem + P_FLOATS + b * CARDS_FLOATS + (warp * RPG) * CSTR;
        #pragma unroll 5
        for (int t = 0; t < 75; t++) {
            ulonglong2 wv = Pq[t * 32 + lane];        // LDS.128 conflict-free
            #pragma unroll
            for (int r = 0; r < RPG; r++) {
                ulonglong2 cv = *(const ulonglong2*)(cb + r * CSTR + 4 * t); // uniform LDS.128
                fma2(acc[r], cv.x, wv.x);
                fma2(acc[r], cv.y, wv.y);
            }
        }
        #pragma unroll
        for (int r = 0; r < RPG; r++) {
            float2 a2 = unpack2(acc[r]);
            apbuf[r * 32 + lane] = a2.x + a2.y + 1.0f;
        }
        __syncthreads();   // all warps done with cards[b]; next iter may overwrite it

        // ---------- phase 2: sparse scores + masked log-softmax ----------
        #pragma unroll 1
        for (int r = 0; r < RPG; r++) {
            const int cn = cnt[r];

            float4 av = ((const float4*)(apbuf + r * 32))[sub];
            const int nch = (cn + 3) >> 2;
            #pragma unroll 2
            for (int ch = 0; ch < nch; ch++) {
                int  j   = ch * 4 + qid;
                bool val = j < cn;
                int  c   = val ? idxbuf[r * IDXCAP + j] : 0;
                float4 wv = *(const float4*)(W + c * A_DIM + sub * 4);
                float p = av.x * wv.x + av.y * wv.y + av.z * wv.z + av.w * wv.w;
                p += __shfl_xor_sync(FULL, p, 1);
                p += __shfl_xor_sync(FULL, p, 2);
                p += __shfl_xor_sync(FULL, p, 4);
                if (val && sub == 0) scbuf[j] = p;
            }
            __syncwarp();

            int  j0 = lane, j1 = lane + 32;
            bool v0 = j0 < cn, v1 = j1 < cn;
            float s0 = v0 ? scbuf[j0] : 0.0f;
            float s1 = v1 ? scbuf[j1] : 0.0f;
            int   c0 = v0 ? idxbuf[r * IDXCAP + j0] : -1;
            int   c1 = v1 ? idxbuf[r * IDXCAP + j1] : -1;

            float m = fmaxf(fmaxf(s0, s1), 0.0f);     // zeros always present in row
            #pragma unroll
            for (int o = 16; o > 0; o >>= 1) m = fmaxf(m, __shfl_xor_sync(FULL, m, o));

            float g0 = (s0 > 0.f) ? 1.f : ((s0 < 0.f) ? -1.f : 0.f);
            float g1 = (s1 > 0.f) ? 1.f : ((s1 < 0.f) ? -1.f : 0.f);
            float sum = g0 * __expf(s0 - m * g0) + g1 * __expf(s1 - m * g1);
            #pragma unroll
            for (int o = 16; o > 0; o >>= 1) sum += __shfl_xor_sync(FULL, sum, o);
            float lse = __logf(sum);

            float* orow = Out + (size_t)(row0 + r) * C_COLS;
            #pragma unroll
            for (int t = 0; t < 3; t++) {
                int gi = lane + 32 * t;
                if (gi < 75) *(float4*)(orow + 4 * gi) = make_float4(0.f, 0.f, 0.f, 0.f);
            }
            __syncwarp();
            if (c0 >= 0) orow[c0] = g0 * ((s0 - m * g0) - lse);
            if (c1 >= 0) orow[c1] = g1 * ((s1 - m * g1) - lse);
        }
        __syncwarp();
    }
}

extern "C" void kernel_launch(void* const* d_in, const int* in_sizes, int n_in,
                              void* d_out, int out_size)
{
    const float* X = (const float*)d_in[0];
    const float* W = (const float*)d_in[1];
    if (n_in >= 2 && in_sizes[0] < in_sizes[1]) {    // defensively order by size
        const float* t = X; X = W; W = t;
    }
    float* Out = (float*)d_out;

    cudaFuncSetAttribute(draftbot_kernel,
                         cudaFuncAttributeMaxDynamicSharedMemorySize, SMEM_BYTES);
    draftbot_kernel<<<GRID, THREADS, SMEM_BYTES>>>(X, W, Out);
}